// round 6
// baseline (speedup 1.0000x reference)
#include <cuda_runtime.h>
#include <cstdint>
#include <cstddef>

#define BB 4
#define CC 256
#define CKD 32
#define NN 4096
#define HH 64
#define WW 64
#define OP 576   // packed projection rows: 256 v + 256 d1 + 32 q + 32 k

// ---------------- scratch (device globals; no allocation allowed) ----------------
__device__ float g_Wp[2][OP][CC];       // packed weights per side
__device__ float g_bp[2][OP];           // packed bias per side
__device__ float g_pk[2][BB][OP][NN];   // packed projection outputs
__device__ float g_d3[2][BB][CC][NN];   // conv3x3 outputs
__device__ float g_o1[BB*CC*NN];
__device__ float g_o2[BB*CC*NN];

// ---------------- helpers --------------------------------------------------------
__device__ __forceinline__ void mma8(float* c,
                                     uint32_t a0, uint32_t a1, uint32_t a2, uint32_t a3,
                                     uint32_t b0, uint32_t b1) {
    asm volatile(
        "mma.sync.aligned.m16n8k8.row.col.f32.tf32.tf32.f32 "
        "{%0,%1,%2,%3}, {%4,%5,%6,%7}, {%8,%9}, {%0,%1,%2,%3};"
        : "+f"(c[0]), "+f"(c[1]), "+f"(c[2]), "+f"(c[3])
        : "r"(a0), "r"(a1), "r"(a2), "r"(a3), "r"(b0), "r"(b1));
}
__device__ __forceinline__ void cpa16(uint32_t dst, const void* src) {
    asm volatile("cp.async.ca.shared.global [%0], [%1], 16;\n" :: "r"(dst), "l"(src));
}
__device__ __forceinline__ void cpa4(uint32_t dst, const void* src) {
    asm volatile("cp.async.ca.shared.global [%0], [%1], 4;\n" :: "r"(dst), "l"(src));
}
__device__ __forceinline__ void cp_commit() { asm volatile("cp.async.commit_group;"); }
__device__ __forceinline__ void cp_wait0()  { asm volatile("cp.async.wait_group 0;"); }

// ---------------- weight packing -------------------------------------------------
__global__ void pack_weights(const float* __restrict__ wv1, const float* __restrict__ bv1,
                             const float* __restrict__ wd1, const float* __restrict__ bd1,
                             const float* __restrict__ wq1, const float* __restrict__ bq1,
                             const float* __restrict__ wk1, const float* __restrict__ bk1,
                             const float* __restrict__ wv2, const float* __restrict__ bv2,
                             const float* __restrict__ wq2, const float* __restrict__ bq2,
                             const float* __restrict__ wk2, const float* __restrict__ bk2)
{
    int row = blockIdx.x;
    int side = blockIdx.y;
    const float *w, *bs; int r;
    if (row < 256)      { w = side ? wv2 : wv1; bs = side ? bv2 : bv1; r = row; }
    else if (row < 512) { w = wd1;              bs = bd1;              r = row - 256; }
    else if (row < 544) { w = side ? wq2 : wq1; bs = side ? bq2 : bq1; r = row - 512; }
    else                { w = side ? wk2 : wk1; bs = side ? bk2 : bk1; r = row - 544; }
    g_Wp[side][row][threadIdx.x] = w[r * CC + threadIdx.x];
    if (threadIdx.x == 0) g_bp[side][row] = bs[r];
}

// ---------------- fused 1x1 projections via tf32 mma -----------------------------
// grid (NN/128, OP/64, 8): z = side*4 + b. 256 threads, 8 warps = 4 m x 2 n-halves.
__global__ __launch_bounds__(256, 2) void proj_mma(const float* __restrict__ X1,
                                                   const float* __restrict__ X2)
{
    __shared__ float Ws[2][64][36];
    __shared__ float Xs[2][16][136];

    const int tid = threadIdx.x;
    const int w = tid >> 5, lane = tid & 31, g = lane >> 2, qb = lane & 3;
    const int mo = w & 3, nh = w >> 2;
    const int n0 = blockIdx.x * 128, o0 = blockIdx.y * 64;
    const int z = blockIdx.z, side = z >> 2, b = z & 3;
    const float* X = (side ? X2 : X1) + (size_t)b * CC * NN;
    const float* Wp = &g_Wp[side][0][0];
    float* Y = &g_pk[side][b][0][0];

    const uint32_t sw = (uint32_t)__cvta_generic_to_shared(&Ws[0][0][0]);
    const uint32_t sx = (uint32_t)__cvta_generic_to_shared(&Xs[0][0][0]);

    const int wo = tid >> 2, wc4 = (tid & 3) * 4;
    auto issue = [&](int buf, int c0) {
        cpa16(sw + (uint32_t)(buf * 2304 + wo * 36 + wc4) * 4,
              Wp + (size_t)(o0 + wo) * CC + c0 + wc4);
#pragma unroll
        for (int it = 0; it < 2; it++) {
            int cid = tid + it * 256;
            int c = cid >> 5, nc = (cid & 31) * 4;
            cpa16(sx + (uint32_t)(buf * 2176 + c * 136 + nc) * 4,
                  X + (size_t)(c0 + c) * NN + n0 + nc);
        }
        cp_commit();
    };

    float acc[8][4];
#pragma unroll
    for (int nt = 0; nt < 8; nt++)
#pragma unroll
        for (int e = 0; e < 4; e++) acc[nt][e] = 0.f;

    issue(0, 0);
    for (int kc = 0; kc < 16; kc++) {
        const int cur = kc & 1;
        cp_wait0();
        __syncthreads();
        if (kc < 15) issue(cur ^ 1, 16 * (kc + 1));
#pragma unroll
        for (int ks = 0; ks < 2; ks++) {
            const int k0 = 8 * ks;
            uint32_t a0 = __float_as_uint(Ws[cur][16 * mo + g][k0 + qb]);
            uint32_t a1 = __float_as_uint(Ws[cur][16 * mo + g + 8][k0 + qb]);
            uint32_t a2 = __float_as_uint(Ws[cur][16 * mo + g][k0 + qb + 4]);
            uint32_t a3 = __float_as_uint(Ws[cur][16 * mo + g + 8][k0 + qb + 4]);
#pragma unroll
            for (int nt = 0; nt < 8; nt++) {
                uint32_t b0 = __float_as_uint(Xs[cur][k0 + qb][64 * nh + 8 * nt + g]);
                uint32_t b1 = __float_as_uint(Xs[cur][k0 + qb + 4][64 * nh + 8 * nt + g]);
                mma8(acc[nt], a0, a1, a2, a3, b0, b1);
            }
        }
        __syncthreads();
    }

    const int olo = o0 + 16 * mo + g, ohi = olo + 8;
    const float blo = g_bp[side][olo], bhi = g_bp[side][ohi];
#pragma unroll
    for (int nt = 0; nt < 8; nt++) {
        int n = n0 + 64 * nh + 8 * nt + 2 * qb;
        float2 v0; v0.x = acc[nt][0] + blo; v0.y = acc[nt][1] + blo;
        *(float2*)(Y + (size_t)olo * NN + n) = v0;
        float2 v1; v1.x = acc[nt][2] + bhi; v1.y = acc[nt][3] + bhi;
        *(float2*)(Y + (size_t)ohi * NN + n) = v1;
    }
}

// ---------------- 3x3 conv via tf32 mma (implicit GEMM) --------------------------
#define CV_SO 100
#define CV_XR 68
#define CV_XC 408
#define CV_WS 6400
#define CV_XS 3264
#define CV_SMEM_BYTES ((2 * (CV_WS + CV_XS)) * 4)   // 77312

__global__ __launch_bounds__(256, 2) void conv3x3_mma(
    const float* __restrict__ X1, const float* __restrict__ X2,
    const float* __restrict__ W3, const float* __restrict__ bias)
{
    extern __shared__ float csm[];
    float* Ws = csm;
    float* Xs = csm + 2 * CV_WS;

    const int tid = threadIdx.x;
    const int w = tid >> 5, lane = tid & 31, g = lane >> 2, qb = lane & 3;
    const int mo = w & 3, sh = w >> 2;
    const int o0 = blockIdx.x * 64;
    const int hg = blockIdx.y;
    const int z = blockIdx.z, side = z >> 2, b = z & 3;
    const float* X = (side ? X2 : X1) + (size_t)b * CC * NN;
    float* Y = &g_d3[side][b][0][0];

    const uint32_t sw = (uint32_t)__cvta_generic_to_shared(Ws);
    const uint32_t sx = (uint32_t)__cvta_generic_to_shared(Xs);

    for (int i = tid; i < 2 * CV_XS; i += 256) Xs[i] = 0.f;
    __syncthreads();

    auto issue = [&](int buf, int c0) {
#pragma unroll
        for (int it = 0; it < 5; it++) {
            int idx = tid + it * 256;
            if (idx < 1152) {
                int o = idx / 18, ch = (idx % 18) * 4;
                cpa16(sw + (uint32_t)(buf * CV_WS + o * CV_SO + ch) * 4,
                      W3 + ((size_t)(o0 + o) * CC + c0) * 9 + ch);
            }
        }
#pragma unroll
        for (int it = 0; it < 12; it++) {
            int idx = tid + it * 256;
            int c = idx / 384, rem = idx - c * 384;
            int r = rem >> 6, wv = rem & 63;
            int h_in = 4 * hg + r - 1;
            if (h_in >= 0 && h_in < HH)
                cpa4(sx + (uint32_t)(buf * CV_XS + c * CV_XC + r * CV_XR + 1 + wv) * 4,
                     X + (size_t)(c0 + c) * NN + h_in * WW + wv);
        }
        cp_commit();
    };

    float acc[16][4];
#pragma unroll
    for (int nt = 0; nt < 16; nt++)
#pragma unroll
        for (int e = 0; e < 4; e++) acc[nt][e] = 0.f;

    issue(0, 0);
    for (int cc = 0; cc < 32; cc++) {
        const int cur = cc & 1;
        cp_wait0();
        __syncthreads();
        if (cc < 31) issue(cur ^ 1, 8 * (cc + 1));
        const float* Wc = Ws + cur * CV_WS;
        const float* Xc = Xs + cur * CV_XS;
#pragma unroll
        for (int ky = 0; ky < 3; ky++) {
#pragma unroll
            for (int kx = 0; kx < 3; kx++) {
                const int tap = ky * 3 + kx;
                uint32_t a0 = __float_as_uint(Wc[(16 * mo + g) * CV_SO + qb * 9 + tap]);
                uint32_t a1 = __float_as_uint(Wc[(16 * mo + g + 8) * CV_SO + qb * 9 + tap]);
                uint32_t a2 = __float_as_uint(Wc[(16 * mo + g) * CV_SO + (qb + 4) * 9 + tap]);
                uint32_t a3 = __float_as_uint(Wc[(16 * mo + g + 8) * CV_SO + (qb + 4) * 9 + tap]);
#pragma unroll
                for (int nt = 0; nt < 16; nt++) {
                    int r = 2 * sh + (nt >> 3) + ky;
                    int col = (nt & 7) * 8 + g + kx;
                    uint32_t b0 = __float_as_uint(Xc[qb * CV_XC + r * CV_XR + col]);
                    uint32_t b1 = __float_as_uint(Xc[(qb + 4) * CV_XC + r * CV_XR + col]);
                    mma8(acc[nt], a0, a1, a2, a3, b0, b1);
                }
            }
        }
        __syncthreads();
    }

    const float blo = bias[o0 + 16 * mo + g], bhi = bias[o0 + 16 * mo + g + 8];
#pragma unroll
    for (int nt = 0; nt < 16; nt++) {
        int h = 4 * hg + 2 * sh + (nt >> 3);
        int wv = (nt & 7) * 8 + 2 * qb;
        size_t base = (size_t)(o0 + 16 * mo + g) * NN + h * WW + wv;
        float2 v0; v0.x = acc[nt][0] + blo; v0.y = acc[nt][1] + blo;
        *(float2*)(Y + base) = v0;
        float2 v1; v1.x = acc[nt][2] + bhi; v1.y = acc[nt][3] + bhi;
        *(float2*)(Y + base + (size_t)8 * NN) = v1;
    }
}

// ---------------- flash attention v5: channel-split for 2 blocks/SM --------------
// grid (NN/64, BB, 2): z = c-half. 256 threads, 8 warps = 4 m-groups x 2 c-quarters.
// Each block computes 128 of 256 output channels; QK+softmax recomputed per half.
#define FB_SMQ 0
#define FB_QSTR 36
#define FB_SMK 2304
#define FB_KSTR 72
#define FB_KBUF 2304                       // 32*72
#define FB_SMV (FB_SMK + 2 * FB_KBUF)      // 6912
#define FB_VSTR 68
#define FB_VBUF 8704                       // 128*68
#define FB_SMEM_FLOATS (FB_SMV + 2 * FB_VBUF)   // 24320
#define FB_SMEM_BYTES (FB_SMEM_FLOATS * 4)      // 97280

__global__ __launch_bounds__(256, 2)
void flashattn_mma(const float* __restrict__ Q, const float* __restrict__ K,
                   const float* __restrict__ V, float* __restrict__ O, size_t bstr)
{
    extern __shared__ float sm[];
    float* Qs = sm + FB_SMQ;

    const int tid  = threadIdx.x;
    const int w    = tid >> 5;
    const int lane = tid & 31;
    const int g    = lane >> 2;
    const int qb   = lane & 3;
    const int wm   = w & 3;
    const int cw   = w >> 2;     // c-quarter within this block's half
    const int i0   = blockIdx.x * 64;
    const int b    = blockIdx.y;
    const int chh  = blockIdx.z; // channel half
    const bool odd = qb & 1;
    const int srcA = (lane & ~3) | (qb >> 1);
    const int srcB = srcA + 2;

    const float* Qb = Q + (size_t)b * bstr;
    const float* Kb = K + (size_t)b * bstr;
    const float* Vb = V + (size_t)b * bstr + (size_t)chh * 128 * NN;
    float* Ob = O + ((size_t)b * CC + (size_t)chh * 128) * NN;

    const uint32_t smb = (uint32_t)__cvta_generic_to_shared(sm);

    // prologue: tile 0 into buffer 0
    {
#pragma unroll
        for (int it = 0; it < 2; it++) {
            int cid = tid + it * 256;
            int d = cid >> 4, jc = (cid & 15) * 4;
            cpa16(smb + (FB_SMK + d * FB_KSTR + jc) * 4, Kb + (size_t)d * NN + jc);
        }
#pragma unroll
        for (int it = 0; it < 8; it++) {
            int cid = tid + it * 256;
            int c = cid >> 4, jc = (cid & 15) * 4;
            cpa16(smb + (FB_SMV + c * FB_VSTR + jc) * 4, Vb + (size_t)c * NN + jc);
        }
        cp_commit();
    }

    for (int idx = tid; idx < 64 * CKD; idx += 256) {
        int i = idx & 63, d = idx >> 6;
        Qs[i * FB_QSTR + d] = Qb[(size_t)d * NN + i0 + i];
    }
    __syncthreads();

    uint32_t aq[4][4];
#pragma unroll
    for (int kk = 0; kk < 4; kk++) {
        const int d0 = 8 * kk;
        const int br = 16 * wm;
        aq[kk][0] = __float_as_uint(Qs[(br + g) * FB_QSTR + d0 + qb]);
        aq[kk][1] = __float_as_uint(Qs[(br + g + 8) * FB_QSTR + d0 + qb]);
        aq[kk][2] = __float_as_uint(Qs[(br + g) * FB_QSTR + d0 + qb + 4]);
        aq[kk][3] = __float_as_uint(Qs[(br + g + 8) * FB_QSTR + d0 + qb + 4]);
    }

    float acc[8][4];
#pragma unroll
    for (int ct = 0; ct < 8; ct++)
#pragma unroll
        for (int e = 0; e < 4; e++) acc[ct][e] = 0.f;

    float mlo = -1e30f, mhi = -1e30f, llo = 0.f, lhi = 0.f;

    for (int t = 0; t < NN / 64; t++) {
        const int cur = t & 1;
        cp_wait0();
        __syncthreads();

        if (t + 1 < NN / 64) {
            const int j0n = (t + 1) * 64;
            const int nb  = 1 - cur;
#pragma unroll
            for (int it = 0; it < 2; it++) {
                int cid = tid + it * 256;
                int d = cid >> 4, jc = (cid & 15) * 4;
                cpa16(smb + (FB_SMK + nb * FB_KBUF + d * FB_KSTR + jc) * 4,
                      Kb + (size_t)d * NN + j0n + jc);
            }
#pragma unroll
            for (int it = 0; it < 8; it++) {
                int cid = tid + it * 256;
                int c = cid >> 4, jc = (cid & 15) * 4;
                cpa16(smb + (FB_SMV + nb * FB_VBUF + c * FB_VSTR + jc) * 4,
                      Vb + (size_t)c * NN + j0n + jc);
            }
            cp_commit();
        }

        const float* Ks = sm + FB_SMK + cur * FB_KBUF;   // [d][72]
        const float* Vs = sm + FB_SMV + cur * FB_VBUF;   // [c][68], c<128

        // ---- S = Q K^T ----
        float s[8][4];
#pragma unroll
        for (int nt = 0; nt < 8; nt++)
#pragma unroll
            for (int e = 0; e < 4; e++) s[nt][e] = 0.f;

#pragma unroll
        for (int kk = 0; kk < 4; kk++) {
            const int d0 = 8 * kk;
#pragma unroll
            for (int nt = 0; nt < 8; nt++) {
                uint32_t b0 = __float_as_uint(Ks[(d0 + qb) * FB_KSTR + 8 * nt + g]);
                uint32_t b1 = __float_as_uint(Ks[(d0 + qb + 4) * FB_KSTR + 8 * nt + g]);
                mma8(s[nt], aq[kk][0], aq[kk][1], aq[kk][2], aq[kk][3], b0, b1);
            }
        }

        // ---- online softmax in registers ----
        {
            float pmlo = -1e30f, pmhi = -1e30f;
#pragma unroll
            for (int nt = 0; nt < 8; nt++) {
                pmlo = fmaxf(pmlo, fmaxf(s[nt][0], s[nt][1]));
                pmhi = fmaxf(pmhi, fmaxf(s[nt][2], s[nt][3]));
            }
            pmlo = fmaxf(pmlo, __shfl_xor_sync(0xffffffffu, pmlo, 1));
            pmlo = fmaxf(pmlo, __shfl_xor_sync(0xffffffffu, pmlo, 2));
            pmhi = fmaxf(pmhi, __shfl_xor_sync(0xffffffffu, pmhi, 1));
            pmhi = fmaxf(pmhi, __shfl_xor_sync(0xffffffffu, pmhi, 2));

            float mlo_n = fmaxf(mlo, pmlo);
            float mhi_n = fmaxf(mhi, pmhi);
            float alo = __expf(mlo - mlo_n);
            float ahi = __expf(mhi - mhi_n);

            float slo = 0.f, shi = 0.f;
#pragma unroll
            for (int nt = 0; nt < 8; nt++) {
                s[nt][0] = __expf(s[nt][0] - mlo_n);
                s[nt][1] = __expf(s[nt][1] - mlo_n);
                s[nt][2] = __expf(s[nt][2] - mhi_n);
                s[nt][3] = __expf(s[nt][3] - mhi_n);
                slo += s[nt][0] + s[nt][1];
                shi += s[nt][2] + s[nt][3];
            }
            slo += __shfl_xor_sync(0xffffffffu, slo, 1);
            slo += __shfl_xor_sync(0xffffffffu, slo, 2);
            shi += __shfl_xor_sync(0xffffffffu, shi, 1);
            shi += __shfl_xor_sync(0xffffffffu, shi, 2);

            llo = llo * alo + slo;
            lhi = lhi * ahi + shi;
            mlo = mlo_n; mhi = mhi_n;

#pragma unroll
            for (int ct = 0; ct < 8; ct++) {
                acc[ct][0] *= alo; acc[ct][1] *= alo;
                acc[ct][2] *= ahi; acc[ct][3] *= ahi;
            }
        }

        // ---- O += P V ----
#pragma unroll
        for (int kk = 0; kk < 8; kk++) {
            float x0 = __shfl_sync(0xffffffffu, s[kk][0], srcA);
            float x1 = __shfl_sync(0xffffffffu, s[kk][1], srcA);
            float y0 = __shfl_sync(0xffffffffu, s[kk][0], srcB);
            float y1 = __shfl_sync(0xffffffffu, s[kk][1], srcB);
            float z0 = __shfl_sync(0xffffffffu, s[kk][2], srcA);
            float z1 = __shfl_sync(0xffffffffu, s[kk][3], srcA);
            float w0 = __shfl_sync(0xffffffffu, s[kk][2], srcB);
            float w1 = __shfl_sync(0xffffffffu, s[kk][3], srcB);
            uint32_t a0 = __float_as_uint(odd ? x1 : x0);
            uint32_t a1 = __float_as_uint(odd ? z1 : z0);
            uint32_t a2 = __float_as_uint(odd ? y1 : y0);
            uint32_t a3 = __float_as_uint(odd ? w1 : w0);

            const int jk = 8 * kk;
#pragma unroll
            for (int ct = 0; ct < 8; ct++) {
                const int c0 = 64 * cw + 8 * ct;
                uint32_t b0 = __float_as_uint(Vs[(c0 + g) * FB_VSTR + jk + qb]);
                uint32_t b1 = __float_as_uint(Vs[(c0 + g) * FB_VSTR + jk + qb + 4]);
                mma8(acc[ct], a0, a1, a2, a3, b0, b1);
            }
        }
    }

    // ---- epilogue: normalize, stage 128c x 64i in smem, coalesced store ----
    const float lilo = 1.f / llo;
    const float lihi = 1.f / lhi;
    float* smO = sm + FB_SMV;   // 128*68 floats fits in V buffer 0

    __syncthreads();
#pragma unroll
    for (int ct = 0; ct < 8; ct++) {
        const int rr = 16 * wm + g;
        const int cl = 64 * cw + 8 * ct + 2 * qb;
        smO[cl * FB_VSTR + rr]           = acc[ct][0] * lilo;
        smO[(cl + 1) * FB_VSTR + rr]     = acc[ct][1] * lilo;
        smO[cl * FB_VSTR + rr + 8]       = acc[ct][2] * lihi;
        smO[(cl + 1) * FB_VSTR + rr + 8] = acc[ct][3] * lihi;
    }
    __syncthreads();
    for (int idx = tid; idx < 128 * 16; idx += 256) {
        int c = idx >> 4, i4 = idx & 15;
        float4 v = *reinterpret_cast<float4*>(smO + c * FB_VSTR + i4 * 4);
        *reinterpret_cast<float4*>(Ob + (size_t)c * NN + i0 + i4 * 4) = v;
    }
}

// ---------------- combine: out = x + gamma*(attn + d1 + d3) ----------------------
__global__ void combine_kernel(const float* __restrict__ x, const float* __restrict__ o,
                               const float* __restrict__ d1, const float* __restrict__ d3,
                               const float* __restrict__ gamma, float* __restrict__ out)
{
    const int b = blockIdx.z;
    const float4* xp = (const float4*)(x + (size_t)b * CC * NN);
    const float4* op = (const float4*)(o + (size_t)b * CC * NN);
    const float4* dp = (const float4*)(d1 + (size_t)b * OP * NN);
    const float4* ep = (const float4*)(d3 + (size_t)b * CC * NN);
    float4* outp = (float4*)(out + (size_t)b * CC * NN);
    const float g = gamma[0];
    int i = blockIdx.x * blockDim.x + threadIdx.x;
    if (i < CC * NN / 4) {
        float4 xv = xp[i], ov = op[i], dv = dp[i], ev = ep[i];
        float4 r;
        r.x = xv.x + g * (ov.x + dv.x + ev.x);
        r.y = xv.y + g * (ov.y + dv.y + ev.y);
        r.z = xv.z + g * (ov.z + dv.z + ev.z);
        r.w = xv.w + g * (ov.w + dv.w + ev.w);
        outp[i] = r;
    }
}

// ---------------- host launcher --------------------------------------------------
extern "C" void kernel_launch(void* const* d_in, const int* in_sizes, int n_in,
                              void* d_out, int out_size)
{
    (void)in_sizes; (void)n_in; (void)out_size;

    const float* x1  = (const float*)d_in[0];
    const float* x2  = (const float*)d_in[1];
    const float* wq1 = (const float*)d_in[2];
    const float* bq1 = (const float*)d_in[3];
    const float* wk1 = (const float*)d_in[4];
    const float* bk1 = (const float*)d_in[5];
    const float* wv1 = (const float*)d_in[6];
    const float* bv1 = (const float*)d_in[7];
    const float* wq2 = (const float*)d_in[8];
    const float* bq2 = (const float*)d_in[9];
    const float* wk2 = (const float*)d_in[10];
    const float* bk2 = (const float*)d_in[11];
    const float* wv2 = (const float*)d_in[12];
    const float* bv2 = (const float*)d_in[13];
    const float* wd1 = (const float*)d_in[14];
    const float* bd1 = (const float*)d_in[15];
    const float* wd3 = (const float*)d_in[16];
    const float* bd3 = (const float*)d_in[17];
    const float* gm1 = (const float*)d_in[18];
    const float* gm2 = (const float*)d_in[19];
    float* out = (float*)d_out;

    float *p_pk, *p_d3, *p_o1, *p_o2;
    cudaGetSymbolAddress((void**)&p_pk, g_pk);
    cudaGetSymbolAddress((void**)&p_d3, g_d3);
    cudaGetSymbolAddress((void**)&p_o1, g_o1);
    cudaGetSymbolAddress((void**)&p_o2, g_o2);

    const size_t side_str = (size_t)BB * OP * NN;
    float* pk0 = p_pk;
    float* pk1 = p_pk + side_str;
    float* d3a = p_d3;
    float* d3b = p_d3 + (size_t)BB * CC * NN;
    const size_t bstr = (size_t)OP * NN;

    cudaFuncSetAttribute(conv3x3_mma,
                         cudaFuncAttributeMaxDynamicSharedMemorySize, CV_SMEM_BYTES);
    cudaFuncSetAttribute(flashattn_mma,
                         cudaFuncAttributeMaxDynamicSharedMemorySize, FB_SMEM_BYTES);

    // 0: pack weights
    pack_weights<<<dim3(OP, 2), 256>>>(wv1, bv1, wd1, bd1, wq1, bq1, wk1, bk1,
                                       wv2, bv2, wq2, bq2, wk2, bk2);
    // 1: fused projections (both sides)
    proj_mma<<<dim3(NN / 128, OP / 64, 8), 256>>>(x1, x2);
    // 2: conv3x3 (both sides)
    conv3x3_mma<<<dim3(CC / 64, HH / 4, 8), 256, CV_SMEM_BYTES>>>(x1, x2, wd3, bd3);
    // 3: attention 1 (queries x1; keys/values x2)
    flashattn_mma<<<dim3(NN / 64, BB, 2), 256, FB_SMEM_BYTES>>>(
        pk0 + (size_t)512 * NN, pk1 + (size_t)544 * NN, pk1, p_o1, bstr);
    // 4: combine out1
    combine_kernel<<<dim3(1024, 1, BB), 256>>>(x1, p_o1, pk0 + (size_t)256 * NN,
                                               d3a, gm1, out);
    // 5: attention 2 (queries x2; keys/values x1)  <-- profiled launch
    flashattn_mma<<<dim3(NN / 64, BB, 2), 256, FB_SMEM_BYTES>>>(
        pk1 + (size_t)512 * NN, pk0 + (size_t)544 * NN, pk0, p_o2, bstr);
    // 6: combine out2
    combine_kernel<<<dim3(1024, 1, BB), 256>>>(x2, p_o2, pk1 + (size_t)256 * NN,
                                               d3b, gm2, out + (size_t)BB * CC * NN);
}

// round 8
// speedup vs baseline: 1.1682x; 1.1682x over previous
#include <cuda_runtime.h>
#include <cstdint>
#include <cstddef>

#define BB 4
#define CC 256
#define CKD 32
#define NN 4096
#define HH 64
#define WW 64
#define OP 576   // packed projection rows: 256 v + 256 d1 + 32 q + 32 k

// ---------------- scratch (device globals; no allocation allowed) ----------------
__device__ float g_Wp[2][OP][CC];       // packed weights per side
__device__ float g_bp[2][OP];           // packed bias per side
__device__ float g_pk[2][BB][OP][NN];   // packed projection outputs
__device__ float g_d3[2][BB][CC][NN];   // conv3x3 outputs
__device__ float g_o1[BB*CC*NN];
__device__ float g_o2[BB*CC*NN];

// ---------------- helpers --------------------------------------------------------
__device__ __forceinline__ void mma8(float* c,
                                     uint32_t a0, uint32_t a1, uint32_t a2, uint32_t a3,
                                     uint32_t b0, uint32_t b1) {
    asm volatile(
        "mma.sync.aligned.m16n8k8.row.col.f32.tf32.tf32.f32 "
        "{%0,%1,%2,%3}, {%4,%5,%6,%7}, {%8,%9}, {%0,%1,%2,%3};"
        : "+f"(c[0]), "+f"(c[1]), "+f"(c[2]), "+f"(c[3])
        : "r"(a0), "r"(a1), "r"(a2), "r"(a3), "r"(b0), "r"(b1));
}
__device__ __forceinline__ void cpa16(uint32_t dst, const void* src) {
    asm volatile("cp.async.ca.shared.global [%0], [%1], 16;\n" :: "r"(dst), "l"(src));
}
__device__ __forceinline__ void cpa4(uint32_t dst, const void* src) {
    asm volatile("cp.async.ca.shared.global [%0], [%1], 4;\n" :: "r"(dst), "l"(src));
}
__device__ __forceinline__ void cp_commit() { asm volatile("cp.async.commit_group;"); }
__device__ __forceinline__ void cp_wait0()  { asm volatile("cp.async.wait_group 0;"); }

// ---------------- weight packing -------------------------------------------------
__global__ void pack_weights(const float* __restrict__ wv1, const float* __restrict__ bv1,
                             const float* __restrict__ wd1, const float* __restrict__ bd1,
                             const float* __restrict__ wq1, const float* __restrict__ bq1,
                             const float* __restrict__ wk1, const float* __restrict__ bk1,
                             const float* __restrict__ wv2, const float* __restrict__ bv2,
                             const float* __restrict__ wq2, const float* __restrict__ bq2,
                             const float* __restrict__ wk2, const float* __restrict__ bk2)
{
    int row = blockIdx.x;
    int side = blockIdx.y;
    const float *w, *bs; int r;
    if (row < 256)      { w = side ? wv2 : wv1; bs = side ? bv2 : bv1; r = row; }
    else if (row < 512) { w = wd1;              bs = bd1;              r = row - 256; }
    else if (row < 544) { w = side ? wq2 : wq1; bs = side ? bq2 : bq1; r = row - 512; }
    else                { w = side ? wk2 : wk1; bs = side ? bk2 : bk1; r = row - 544; }
    g_Wp[side][row][threadIdx.x] = w[r * CC + threadIdx.x];
    if (threadIdx.x == 0) g_bp[side][row] = bs[r];
}

// ---------------- fused 1x1 projections via tf32 mma -----------------------------
// grid (NN/128, OP/64, 8): z = side*4 + b. 256 threads, 8 warps = 4 m x 2 n-halves.
__global__ __launch_bounds__(256, 2) void proj_mma(const float* __restrict__ X1,
                                                   const float* __restrict__ X2)
{
    __shared__ float Ws[2][64][36];
    __shared__ float Xs[2][16][136];

    const int tid = threadIdx.x;
    const int w = tid >> 5, lane = tid & 31, g = lane >> 2, qb = lane & 3;
    const int mo = w & 3, nh = w >> 2;
    const int n0 = blockIdx.x * 128, o0 = blockIdx.y * 64;
    const int z = blockIdx.z, side = z >> 2, b = z & 3;
    const float* X = (side ? X2 : X1) + (size_t)b * CC * NN;
    const float* Wp = &g_Wp[side][0][0];
    float* Y = &g_pk[side][b][0][0];

    const uint32_t sw = (uint32_t)__cvta_generic_to_shared(&Ws[0][0][0]);
    const uint32_t sx = (uint32_t)__cvta_generic_to_shared(&Xs[0][0][0]);

    const int wo = tid >> 2, wc4 = (tid & 3) * 4;
    auto issue = [&](int buf, int c0) {
        cpa16(sw + (uint32_t)(buf * 2304 + wo * 36 + wc4) * 4,
              Wp + (size_t)(o0 + wo) * CC + c0 + wc4);
#pragma unroll
        for (int it = 0; it < 2; it++) {
            int cid = tid + it * 256;
            int c = cid >> 5, nc = (cid & 31) * 4;
            cpa16(sx + (uint32_t)(buf * 2176 + c * 136 + nc) * 4,
                  X + (size_t)(c0 + c) * NN + n0 + nc);
        }
        cp_commit();
    };

    float acc[8][4];
#pragma unroll
    for (int nt = 0; nt < 8; nt++)
#pragma unroll
        for (int e = 0; e < 4; e++) acc[nt][e] = 0.f;

    issue(0, 0);
    for (int kc = 0; kc < 16; kc++) {
        const int cur = kc & 1;
        cp_wait0();
        __syncthreads();
        if (kc < 15) issue(cur ^ 1, 16 * (kc + 1));
#pragma unroll
        for (int ks = 0; ks < 2; ks++) {
            const int k0 = 8 * ks;
            uint32_t a0 = __float_as_uint(Ws[cur][16 * mo + g][k0 + qb]);
            uint32_t a1 = __float_as_uint(Ws[cur][16 * mo + g + 8][k0 + qb]);
            uint32_t a2 = __float_as_uint(Ws[cur][16 * mo + g][k0 + qb + 4]);
            uint32_t a3 = __float_as_uint(Ws[cur][16 * mo + g + 8][k0 + qb + 4]);
#pragma unroll
            for (int nt = 0; nt < 8; nt++) {
                uint32_t b0 = __float_as_uint(Xs[cur][k0 + qb][64 * nh + 8 * nt + g]);
                uint32_t b1 = __float_as_uint(Xs[cur][k0 + qb + 4][64 * nh + 8 * nt + g]);
                mma8(acc[nt], a0, a1, a2, a3, b0, b1);
            }
        }
        __syncthreads();
    }

    const int olo = o0 + 16 * mo + g, ohi = olo + 8;
    const float blo = g_bp[side][olo], bhi = g_bp[side][ohi];
#pragma unroll
    for (int nt = 0; nt < 8; nt++) {
        int n = n0 + 64 * nh + 8 * nt + 2 * qb;
        float2 v0; v0.x = acc[nt][0] + blo; v0.y = acc[nt][1] + blo;
        *(float2*)(Y + (size_t)olo * NN + n) = v0;
        float2 v1; v1.x = acc[nt][2] + bhi; v1.y = acc[nt][3] + bhi;
        *(float2*)(Y + (size_t)ohi * NN + n) = v1;
    }
}

// ---------------- 3x3 conv via tf32 mma (implicit GEMM) --------------------------
#define CV_SO 100
#define CV_XR 68
#define CV_XC 408
#define CV_WS 6400
#define CV_XS 3264
#define CV_SMEM_BYTES ((2 * (CV_WS + CV_XS)) * 4)   // 77312

__global__ __launch_bounds__(256, 2) void conv3x3_mma(
    const float* __restrict__ X1, const float* __restrict__ X2,
    const float* __restrict__ W3, const float* __restrict__ bias)
{
    extern __shared__ float csm[];
    float* Ws = csm;
    float* Xs = csm + 2 * CV_WS;

    const int tid = threadIdx.x;
    const int w = tid >> 5, lane = tid & 31, g = lane >> 2, qb = lane & 3;
    const int mo = w & 3, sh = w >> 2;
    const int o0 = blockIdx.x * 64;
    const int hg = blockIdx.y;
    const int z = blockIdx.z, side = z >> 2, b = z & 3;
    const float* X = (side ? X2 : X1) + (size_t)b * CC * NN;
    float* Y = &g_d3[side][b][0][0];

    const uint32_t sw = (uint32_t)__cvta_generic_to_shared(Ws);
    const uint32_t sx = (uint32_t)__cvta_generic_to_shared(Xs);

    for (int i = tid; i < 2 * CV_XS; i += 256) Xs[i] = 0.f;
    __syncthreads();

    auto issue = [&](int buf, int c0) {
#pragma unroll
        for (int it = 0; it < 5; it++) {
            int idx = tid + it * 256;
            if (idx < 1152) {
                int o = idx / 18, ch = (idx % 18) * 4;
                cpa16(sw + (uint32_t)(buf * CV_WS + o * CV_SO + ch) * 4,
                      W3 + ((size_t)(o0 + o) * CC + c0) * 9 + ch);
            }
        }
#pragma unroll
        for (int it = 0; it < 12; it++) {
            int idx = tid + it * 256;
            int c = idx / 384, rem = idx - c * 384;
            int r = rem >> 6, wv = rem & 63;
            int h_in = 4 * hg + r - 1;
            if (h_in >= 0 && h_in < HH)
                cpa4(sx + (uint32_t)(buf * CV_XS + c * CV_XC + r * CV_XR + 1 + wv) * 4,
                     X + (size_t)(c0 + c) * NN + h_in * WW + wv);
        }
        cp_commit();
    };

    float acc[16][4];
#pragma unroll
    for (int nt = 0; nt < 16; nt++)
#pragma unroll
        for (int e = 0; e < 4; e++) acc[nt][e] = 0.f;

    issue(0, 0);
    for (int cc = 0; cc < 32; cc++) {
        const int cur = cc & 1;
        cp_wait0();
        __syncthreads();
        if (cc < 31) issue(cur ^ 1, 8 * (cc + 1));
        const float* Wc = Ws + cur * CV_WS;
        const float* Xc = Xs + cur * CV_XS;
#pragma unroll
        for (int ky = 0; ky < 3; ky++) {
#pragma unroll
            for (int kx = 0; kx < 3; kx++) {
                const int tap = ky * 3 + kx;
                uint32_t a0 = __float_as_uint(Wc[(16 * mo + g) * CV_SO + qb * 9 + tap]);
                uint32_t a1 = __float_as_uint(Wc[(16 * mo + g + 8) * CV_SO + qb * 9 + tap]);
                uint32_t a2 = __float_as_uint(Wc[(16 * mo + g) * CV_SO + (qb + 4) * 9 + tap]);
                uint32_t a3 = __float_as_uint(Wc[(16 * mo + g + 8) * CV_SO + (qb + 4) * 9 + tap]);
#pragma unroll
                for (int nt = 0; nt < 16; nt++) {
                    int r = 2 * sh + (nt >> 3) + ky;
                    int col = (nt & 7) * 8 + g + kx;
                    uint32_t b0 = __float_as_uint(Xc[qb * CV_XC + r * CV_XR + col]);
                    uint32_t b1 = __float_as_uint(Xc[(qb + 4) * CV_XC + r * CV_XR + col]);
                    mma8(acc[nt], a0, a1, a2, a3, b0, b1);
                }
            }
        }
        __syncthreads();
    }

    const float blo = bias[o0 + 16 * mo + g], bhi = bias[o0 + 16 * mo + g + 8];
#pragma unroll
    for (int nt = 0; nt < 16; nt++) {
        int h = 4 * hg + 2 * sh + (nt >> 3);
        int wv = (nt & 7) * 8 + 2 * qb;
        size_t base = (size_t)(o0 + 16 * mo + g) * NN + h * WW + wv;
        float2 v0; v0.x = acc[nt][0] + blo; v0.y = acc[nt][1] + blo;
        *(float2*)(Y + base) = v0;
        float2 v1; v1.x = acc[nt][2] + bhi; v1.y = acc[nt][3] + bhi;
        *(float2*)(Y + base + (size_t)8 * NN) = v1;
    }
}

// ---------------- flash attention v6b: BN=32, 2 blocks/SM, no duplication --------
// grid (NN/64, BB). 256 threads, 8 warps = 4 m-groups x 2 c-halves.
// BM=64, BN=32. Full 256 channels per block. smem ~91 KB -> 2 blocks/SM.
#define F6_SMQ 0
#define F6_QSTR 36
#define F6_SMK 2304
#define F6_KSTR 40
#define F6_KBUF 1280                       // 32*40
#define F6_SMV (F6_SMK + 2 * F6_KBUF)      // 4864
#define F6_VSTR 36
#define F6_VBUF 9216                       // 256*36
#define F6_SMEM_FLOATS (F6_SMV + 2 * F6_VBUF)   // 23296
#define F6_SMEM_BYTES (F6_SMEM_FLOATS * 4)      // 93184

__global__ __launch_bounds__(256, 2)
void flashattn_mma(const float* __restrict__ Q, const float* __restrict__ K,
                   const float* __restrict__ V, float* __restrict__ O, size_t bstr)
{
    extern __shared__ float sm[];
    float* Qs = sm + F6_SMQ;

    const int tid  = threadIdx.x;
    const int w    = tid >> 5;
    const int lane = tid & 31;
    const int g    = lane >> 2;
    const int qb   = lane & 3;
    const int wm   = w & 3;
    const int cw   = w >> 2;
    const int i0   = blockIdx.x * 64;
    const int b    = blockIdx.y;
    const bool odd = qb & 1;
    const int srcA = (lane & ~3) | (qb >> 1);
    const int srcB = srcA + 2;

    const float* Qb = Q + (size_t)b * bstr;
    const float* Kb = K + (size_t)b * bstr;
    const float* Vb = V + (size_t)b * bstr;

    const uint32_t smb = (uint32_t)__cvta_generic_to_shared(sm);

    // issue K (32x32) + V (256x32) tile for column block j0 into buffer buf
    auto issue = [&](int buf, int j0) {
        {   // K: 256 16B-chunks, 1 per thread
            int d = tid >> 3, jc = (tid & 7) * 4;
            cpa16(smb + (uint32_t)(F6_SMK + buf * F6_KBUF + d * F6_KSTR + jc) * 4,
                  Kb + (size_t)d * NN + j0 + jc);
        }
#pragma unroll
        for (int it = 0; it < 8; it++) {   // V: 2048 chunks (256c x 8jc), 8 per thread
            int cid = tid + it * 256;
            int c = cid >> 3, jc = (cid & 7) * 4;
            cpa16(smb + (uint32_t)(F6_SMV + buf * F6_VBUF + c * F6_VSTR + jc) * 4,
                  Vb + (size_t)c * NN + j0 + jc);
        }
        cp_commit();
    };

    issue(0, 0);

    // Q tile (64 x 32) transposed -> [i][d]
    for (int idx = tid; idx < 64 * CKD; idx += 256) {
        int i = idx & 63, d = idx >> 6;
        Qs[i * F6_QSTR + d] = Qb[(size_t)d * NN + i0 + i];
    }
    __syncthreads();

    uint32_t aq[4][4];
#pragma unroll
    for (int kk = 0; kk < 4; kk++) {
        const int d0 = 8 * kk;
        const int br = 16 * wm;
        aq[kk][0] = __float_as_uint(Qs[(br + g) * F6_QSTR + d0 + qb]);
        aq[kk][1] = __float_as_uint(Qs[(br + g + 8) * F6_QSTR + d0 + qb]);
        aq[kk][2] = __float_as_uint(Qs[(br + g) * F6_QSTR + d0 + qb + 4]);
        aq[kk][3] = __float_as_uint(Qs[(br + g + 8) * F6_QSTR + d0 + qb + 4]);
    }

    float acc[16][4];
#pragma unroll
    for (int ct = 0; ct < 16; ct++)
#pragma unroll
        for (int e = 0; e < 4; e++) acc[ct][e] = 0.f;

    float mlo = -1e30f, mhi = -1e30f, llo = 0.f, lhi = 0.f;

    for (int t = 0; t < NN / 32; t++) {
        const int cur = t & 1;
        cp_wait0();
        __syncthreads();
        if (t + 1 < NN / 32) issue(cur ^ 1, 32 * (t + 1));

        const float* Ks = sm + F6_SMK + cur * F6_KBUF;   // [d][40]
        const float* Vs = sm + F6_SMV + cur * F6_VBUF;   // [c][36]

        // ---- S = Q K^T (16 rows x 32 cols per warp) ----
        float s[4][4];
#pragma unroll
        for (int nt = 0; nt < 4; nt++)
#pragma unroll
            for (int e = 0; e < 4; e++) s[nt][e] = 0.f;

#pragma unroll
        for (int kk = 0; kk < 4; kk++) {
            const int d0 = 8 * kk;
#pragma unroll
            for (int nt = 0; nt < 4; nt++) {
                uint32_t b0 = __float_as_uint(Ks[(d0 + qb) * F6_KSTR + 8 * nt + g]);
                uint32_t b1 = __float_as_uint(Ks[(d0 + qb + 4) * F6_KSTR + 8 * nt + g]);
                mma8(s[nt], aq[kk][0], aq[kk][1], aq[kk][2], aq[kk][3], b0, b1);
            }
        }

        // ---- online softmax in registers ----
        {
            float pmlo = -1e30f, pmhi = -1e30f;
#pragma unroll
            for (int nt = 0; nt < 4; nt++) {
                pmlo = fmaxf(pmlo, fmaxf(s[nt][0], s[nt][1]));
                pmhi = fmaxf(pmhi, fmaxf(s[nt][2], s[nt][3]));
            }
            pmlo = fmaxf(pmlo, __shfl_xor_sync(0xffffffffu, pmlo, 1));
            pmlo = fmaxf(pmlo, __shfl_xor_sync(0xffffffffu, pmlo, 2));
            pmhi = fmaxf(pmhi, __shfl_xor_sync(0xffffffffu, pmhi, 1));
            pmhi = fmaxf(pmhi, __shfl_xor_sync(0xffffffffu, pmhi, 2));

            float mlo_n = fmaxf(mlo, pmlo);
            float mhi_n = fmaxf(mhi, pmhi);
            float alo = __expf(mlo - mlo_n);
            float ahi = __expf(mhi - mhi_n);

            float slo = 0.f, shi = 0.f;
#pragma unroll
            for (int nt = 0; nt < 4; nt++) {
                s[nt][0] = __expf(s[nt][0] - mlo_n);
                s[nt][1] = __expf(s[nt][1] - mlo_n);
                s[nt][2] = __expf(s[nt][2] - mhi_n);
                s[nt][3] = __expf(s[nt][3] - mhi_n);
                slo += s[nt][0] + s[nt][1];
                shi += s[nt][2] + s[nt][3];
            }
            slo += __shfl_xor_sync(0xffffffffu, slo, 1);
            slo += __shfl_xor_sync(0xffffffffu, slo, 2);
            shi += __shfl_xor_sync(0xffffffffu, shi, 1);
            shi += __shfl_xor_sync(0xffffffffu, shi, 2);

            llo = llo * alo + slo;
            lhi = lhi * ahi + shi;
            mlo = mlo_n; mhi = mhi_n;

#pragma unroll
            for (int ct = 0; ct < 16; ct++) {
                acc[ct][0] *= alo; acc[ct][1] *= alo;
                acc[ct][2] *= ahi; acc[ct][3] *= ahi;
            }
        }

        // ---- O += P V (C-frag -> A-frag permute, 4 k-steps) ----
#pragma unroll
        for (int kk = 0; kk < 4; kk++) {
            float x0 = __shfl_sync(0xffffffffu, s[kk][0], srcA);
            float x1 = __shfl_sync(0xffffffffu, s[kk][1], srcA);
            float y0 = __shfl_sync(0xffffffffu, s[kk][0], srcB);
            float y1 = __shfl_sync(0xffffffffu, s[kk][1], srcB);
            float z0 = __shfl_sync(0xffffffffu, s[kk][2], srcA);
            float z1 = __shfl_sync(0xffffffffu, s[kk][3], srcA);
            float w0 = __shfl_sync(0xffffffffu, s[kk][2], srcB);
            float w1 = __shfl_sync(0xffffffffu, s[kk][3], srcB);
            uint32_t a0 = __float_as_uint(odd ? x1 : x0);
            uint32_t a1 = __float_as_uint(odd ? z1 : z0);
            uint32_t a2 = __float_as_uint(odd ? y1 : y0);
            uint32_t a3 = __float_as_uint(odd ? w1 : w0);

            const int jk = 8 * kk;
#pragma unroll
            for (int ct = 0; ct < 16; ct++) {
                const int c0 = 128 * cw + 8 * ct;
                uint32_t b0 = __float_as_uint(Vs[(c0 + g) * F6_VSTR + jk + qb]);
                uint32_t b1 = __float_as_uint(Vs[(c0 + g) * F6_VSTR + jk + qb + 4]);
                mma8(acc[ct], a0, a1, a2, a3, b0, b1);
            }
        }
    }
    __syncthreads();

    // ---- epilogue: normalize, stage via smem (reuse V buffers), store ----
    const float lilo = 1.f / llo;
    const float lihi = 1.f / lhi;
    float* smO = sm + F6_SMV;   // [128 c][68] = 8704 <= 18432 (both V buffers)

    for (int p = 0; p < 2; p++) {
        __syncthreads();
        if (cw == p) {
#pragma unroll
            for (int ct = 0; ct < 16; ct++) {
                const int rr = 16 * wm + g;
                const int cl = 8 * ct + 2 * qb;
                smO[cl * 68 + rr]           = acc[ct][0] * lilo;
                smO[(cl + 1) * 68 + rr]     = acc[ct][1] * lilo;
                smO[cl * 68 + rr + 8]       = acc[ct][2] * lihi;
                smO[(cl + 1) * 68 + rr + 8] = acc[ct][3] * lihi;
            }
        }
        __syncthreads();
        for (int idx = tid; idx < 128 * 16; idx += 256) {
            int c = idx >> 4, i4 = idx & 15;
            float4 v = *reinterpret_cast<float4*>(smO + c * 68 + i4 * 4);
            *reinterpret_cast<float4*>(
                O + ((size_t)(b * CC + 128 * p + c)) * NN + i0 + i4 * 4) = v;
        }
    }
}

// ---------------- combine: out = x + gamma*(attn + d1 + d3) ----------------------
__global__ void combine_kernel(const float* __restrict__ x, const float* __restrict__ o,
                               const float* __restrict__ d1, const float* __restrict__ d3,
                               const float* __restrict__ gamma, float* __restrict__ out)
{
    const int b = blockIdx.z;
    const float4* xp = (const float4*)(x + (size_t)b * CC * NN);
    const float4* op = (const float4*)(o + (size_t)b * CC * NN);
    const float4* dp = (const float4*)(d1 + (size_t)b * OP * NN);
    const float4* ep = (const float4*)(d3 + (size_t)b * CC * NN);
    float4* outp = (float4*)(out + (size_t)b * CC * NN);
    const float g = gamma[0];
    int i = blockIdx.x * blockDim.x + threadIdx.x;
    if (i < CC * NN / 4) {
        float4 xv = xp[i], ov = op[i], dv = dp[i], ev = ep[i];
        float4 r;
        r.x = xv.x + g * (ov.x + dv.x + ev.x);
        r.y = xv.y + g * (ov.y + dv.y + ev.y);
        r.z = xv.z + g * (ov.z + dv.z + ev.z);
        r.w = xv.w + g * (ov.w + dv.w + ev.w);
        outp[i] = r;
    }
}

// ---------------- host launcher --------------------------------------------------
extern "C" void kernel_launch(void* const* d_in, const int* in_sizes, int n_in,
                              void* d_out, int out_size)
{
    (void)in_sizes; (void)n_in; (void)out_size;

    const float* x1  = (const float*)d_in[0];
    const float* x2  = (const float*)d_in[1];
    const float* wq1 = (const float*)d_in[2];
    const float* bq1 = (const float*)d_in[3];
    const float* wk1 = (const float*)d_in[4];
    const float* bk1 = (const float*)d_in[5];
    const float* wv1 = (const float*)d_in[6];
    const float* bv1 = (const float*)d_in[7];
    const float* wq2 = (const float*)d_in[8];
    const float* bq2 = (const float*)d_in[9];
    const float* wk2 = (const float*)d_in[10];
    const float* bk2 = (const float*)d_in[11];
    const float* wv2 = (const float*)d_in[12];
    const float* bv2 = (const float*)d_in[13];
    const float* wd1 = (const float*)d_in[14];
    const float* bd1 = (const float*)d_in[15];
    const float* wd3 = (const float*)d_in[16];
    const float* bd3 = (const float*)d_in[17];
    const float* gm1 = (const float*)d_in[18];
    const float* gm2 = (const float*)d_in[19];
    float* out = (float*)d_out;

    float *p_pk, *p_d3, *p_o1, *p_o2;
    cudaGetSymbolAddress((void**)&p_pk, g_pk);
    cudaGetSymbolAddress((void**)&p_d3, g_d3);
    cudaGetSymbolAddress((void**)&p_o1, g_o1);
    cudaGetSymbolAddress((void**)&p_o2, g_o2);

    const size_t side_str = (size_t)BB * OP * NN;
    float* pk0 = p_pk;
    float* pk1 = p_pk + side_str;
    float* d3a = p_d3;
    float* d3b = p_d3 + (size_t)BB * CC * NN;
    const size_t bstr = (size_t)OP * NN;

    cudaFuncSetAttribute(conv3x3_mma,
                         cudaFuncAttributeMaxDynamicSharedMemorySize, CV_SMEM_BYTES);
    cudaFuncSetAttribute(flashattn_mma,
                         cudaFuncAttributeMaxDynamicSharedMemorySize, F6_SMEM_BYTES);

    // 0: pack weights
    pack_weights<<<dim3(OP, 2), 256>>>(wv1, bv1, wd1, bd1, wq1, bq1, wk1, bk1,
                                       wv2, bv2, wq2, bq2, wk2, bk2);
    // 1: fused projections (both sides)
    proj_mma<<<dim3(NN / 128, OP / 64, 8), 256>>>(x1, x2);
    // 2: conv3x3 (both sides)
    conv3x3_mma<<<dim3(CC / 64, HH / 4, 8), 256, CV_SMEM_BYTES>>>(x1, x2, wd3, bd3);
    // 3: attention 1 (queries x1; keys/values x2)
    flashattn_mma<<<dim3(NN / 64, BB), 256, F6_SMEM_BYTES>>>(
        pk0 + (size_t)512 * NN, pk1 + (size_t)544 * NN, pk1, p_o1, bstr);
    // 4: combine out1
    combine_kernel<<<dim3(1024, 1, BB), 256>>>(x1, p_o1, pk0 + (size_t)256 * NN,
                                               d3a, gm1, out);
    // 5: attention 2 (queries x2; keys/values x1)  <-- profiled launch
    flashattn_mma<<<dim3(NN / 64, BB), 256, F6_SMEM_BYTES>>>(
        pk1 + (size_t)512 * NN, pk0 + (size_t)544 * NN, pk0, p_o2, bstr);
    // 6: combine out2
    combine_kernel<<<dim3(1024, 1, BB), 256>>>(x2, p_o2, pk1 + (size_t)256 * NN,
                                               d3b, gm2, out + (size_t)BB * CC * NN);
}

// round 10
// speedup vs baseline: 1.2156x; 1.0406x over previous
#include <cuda_runtime.h>
#include <cstdint>
#include <cstddef>

#define BB 4
#define CC 256
#define CKD 32
#define NN 4096
#define HH 64
#define WW 64
#define OP 576   // packed projection rows: 256 v + 256 d1 + 32 q + 32 k

// ---------------- scratch (device globals; no allocation allowed) ----------------
__device__ float g_Wp[2][OP][CC];       // packed weights per side
__device__ float g_bp[2][OP];           // packed bias per side
__device__ float g_pk[2][BB][OP][NN];   // packed projection outputs
__device__ float g_d3[2][BB][CC][NN];   // conv3x3 outputs
__device__ float g_o1[BB*CC*NN];
__device__ float g_o2[BB*CC*NN];

// ---------------- helpers --------------------------------------------------------
__device__ __forceinline__ void mma8(float* c,
                                     uint32_t a0, uint32_t a1, uint32_t a2, uint32_t a3,
                                     uint32_t b0, uint32_t b1) {
    asm volatile(
        "mma.sync.aligned.m16n8k8.row.col.f32.tf32.tf32.f32 "
        "{%0,%1,%2,%3}, {%4,%5,%6,%7}, {%8,%9}, {%0,%1,%2,%3};"
        : "+f"(c[0]), "+f"(c[1]), "+f"(c[2]), "+f"(c[3])
        : "r"(a0), "r"(a1), "r"(a2), "r"(a3), "r"(b0), "r"(b1));
}
__device__ __forceinline__ void ldsm4(uint32_t& r0, uint32_t& r1, uint32_t& r2,
                                      uint32_t& r3, uint32_t addr) {
    asm volatile("ldmatrix.sync.aligned.m8n8.x4.shared.b16 {%0,%1,%2,%3}, [%4];"
                 : "=r"(r0), "=r"(r1), "=r"(r2), "=r"(r3) : "r"(addr));
}
__device__ __forceinline__ void cpa16(uint32_t dst, const void* src) {
    asm volatile("cp.async.ca.shared.global [%0], [%1], 16;\n" :: "r"(dst), "l"(src));
}
__device__ __forceinline__ void cpa4(uint32_t dst, const void* src) {
    asm volatile("cp.async.ca.shared.global [%0], [%1], 4;\n" :: "r"(dst), "l"(src));
}
__device__ __forceinline__ void cp_commit() { asm volatile("cp.async.commit_group;"); }
__device__ __forceinline__ void cp_wait0()  { asm volatile("cp.async.wait_group 0;"); }

// ---------------- weight packing (one side per launch) ---------------------------
__global__ void pack_weights(const float* __restrict__ wv, const float* __restrict__ bv,
                             const float* __restrict__ wd1, const float* __restrict__ bd1,
                             const float* __restrict__ wq, const float* __restrict__ bq,
                             const float* __restrict__ wk, const float* __restrict__ bk,
                             int side)
{
    int row = blockIdx.x;
    const float *w, *bs; int r;
    if (row < 256)      { w = wv;  bs = bv;  r = row; }
    else if (row < 512) { w = wd1; bs = bd1; r = row - 256; }
    else if (row < 544) { w = wq;  bs = bq;  r = row - 512; }
    else                { w = wk;  bs = bk;  r = row - 544; }
    g_Wp[side][row][threadIdx.x] = w[r * CC + threadIdx.x];
    if (threadIdx.x == 0) g_bp[side][row] = bs[r];
}

// ---------------- fused 1x1 projections via tf32 mma -----------------------------
// grid (NN/128, OP/64, 8): z = side*4 + b. 256 threads, 8 warps = 4 m x 2 n-halves.
__global__ __launch_bounds__(256, 2) void proj_mma(const float* __restrict__ X1,
                                                   const float* __restrict__ X2)
{
    __shared__ float Ws[2][64][36];
    __shared__ float Xs[2][16][136];

    const int tid = threadIdx.x;
    const int w = tid >> 5, lane = tid & 31, g = lane >> 2, qb = lane & 3;
    const int mo = w & 3, nh = w >> 2;
    const int n0 = blockIdx.x * 128, o0 = blockIdx.y * 64;
    const int z = blockIdx.z, side = z >> 2, b = z & 3;
    const float* X = (side ? X2 : X1) + (size_t)b * CC * NN;
    const float* Wp = &g_Wp[side][0][0];
    float* Y = &g_pk[side][b][0][0];

    const uint32_t sw = (uint32_t)__cvta_generic_to_shared(&Ws[0][0][0]);
    const uint32_t sx = (uint32_t)__cvta_generic_to_shared(&Xs[0][0][0]);

    const int wo = tid >> 2, wc4 = (tid & 3) * 4;
    auto issue = [&](int buf, int c0) {
        cpa16(sw + (uint32_t)(buf * 2304 + wo * 36 + wc4) * 4,
              Wp + (size_t)(o0 + wo) * CC + c0 + wc4);
#pragma unroll
        for (int it = 0; it < 2; it++) {
            int cid = tid + it * 256;
            int c = cid >> 5, nc = (cid & 31) * 4;
            cpa16(sx + (uint32_t)(buf * 2176 + c * 136 + nc) * 4,
                  X + (size_t)(c0 + c) * NN + n0 + nc);
        }
        cp_commit();
    };

    float acc[8][4];
#pragma unroll
    for (int nt = 0; nt < 8; nt++)
#pragma unroll
        for (int e = 0; e < 4; e++) acc[nt][e] = 0.f;

    issue(0, 0);
    for (int kc = 0; kc < 16; kc++) {
        const int cur = kc & 1;
        cp_wait0();
        __syncthreads();
        if (kc < 15) issue(cur ^ 1, 16 * (kc + 1));
#pragma unroll
        for (int ks = 0; ks < 2; ks++) {
            const int k0 = 8 * ks;
            uint32_t a0 = __float_as_uint(Ws[cur][16 * mo + g][k0 + qb]);
            uint32_t a1 = __float_as_uint(Ws[cur][16 * mo + g + 8][k0 + qb]);
            uint32_t a2 = __float_as_uint(Ws[cur][16 * mo + g][k0 + qb + 4]);
            uint32_t a3 = __float_as_uint(Ws[cur][16 * mo + g + 8][k0 + qb + 4]);
#pragma unroll
            for (int nt = 0; nt < 8; nt++) {
                uint32_t b0 = __float_as_uint(Xs[cur][k0 + qb][64 * nh + 8 * nt + g]);
                uint32_t b1 = __float_as_uint(Xs[cur][k0 + qb + 4][64 * nh + 8 * nt + g]);
                mma8(acc[nt], a0, a1, a2, a3, b0, b1);
            }
        }
        __syncthreads();
    }

    const int olo = o0 + 16 * mo + g, ohi = olo + 8;
    const float blo = g_bp[side][olo], bhi = g_bp[side][ohi];
#pragma unroll
    for (int nt = 0; nt < 8; nt++) {
        int n = n0 + 64 * nh + 8 * nt + 2 * qb;
        float2 v0; v0.x = acc[nt][0] + blo; v0.y = acc[nt][1] + blo;
        *(float2*)(Y + (size_t)olo * NN + n) = v0;
        float2 v1; v1.x = acc[nt][2] + bhi; v1.y = acc[nt][3] + bhi;
        *(float2*)(Y + (size_t)ohi * NN + n) = v1;
    }
}

// ---------------- 3x3 conv via tf32 mma (implicit GEMM, one side per launch) -----
#define CV_SO 100
#define CV_XR 68
#define CV_XC 408
#define CV_WS 6400
#define CV_XS 3264
#define CV_SMEM_BYTES ((2 * (CV_WS + CV_XS)) * 4)   // 77312

__global__ __launch_bounds__(256, 2) void conv3x3_mma(
    const float* __restrict__ Xin, float* __restrict__ Yout,
    const float* __restrict__ W3, const float* __restrict__ bias)
{
    extern __shared__ float csm[];
    float* Ws = csm;
    float* Xs = csm + 2 * CV_WS;

    const int tid = threadIdx.x;
    const int w = tid >> 5, lane = tid & 31, g = lane >> 2, qb = lane & 3;
    const int mo = w & 3, sh = w >> 2;
    const int o0 = blockIdx.x * 64;
    const int hg = blockIdx.y;
    const int b = blockIdx.z;
    const float* X = Xin + (size_t)b * CC * NN;
    float* Y = Yout + (size_t)b * CC * NN;

    const uint32_t sw = (uint32_t)__cvta_generic_to_shared(Ws);
    const uint32_t sx = (uint32_t)__cvta_generic_to_shared(Xs);

    for (int i = tid; i < 2 * CV_XS; i += 256) Xs[i] = 0.f;
    __syncthreads();

    auto issue = [&](int buf, int c0) {
#pragma unroll
        for (int it = 0; it < 5; it++) {
            int idx = tid + it * 256;
            if (idx < 1152) {
                int o = idx / 18, ch = (idx % 18) * 4;
                cpa16(sw + (uint32_t)(buf * CV_WS + o * CV_SO + ch) * 4,
                      W3 + ((size_t)(o0 + o) * CC + c0) * 9 + ch);
            }
        }
#pragma unroll
        for (int it = 0; it < 12; it++) {
            int idx = tid + it * 256;
            int c = idx / 384, rem = idx - c * 384;
            int r = rem >> 6, wv = rem & 63;
            int h_in = 4 * hg + r - 1;
            if (h_in >= 0 && h_in < HH)
                cpa4(sx + (uint32_t)(buf * CV_XS + c * CV_XC + r * CV_XR + 1 + wv) * 4,
                     X + (size_t)(c0 + c) * NN + h_in * WW + wv);
        }
        cp_commit();
    };

    float acc[16][4];
#pragma unroll
    for (int nt = 0; nt < 16; nt++)
#pragma unroll
        for (int e = 0; e < 4; e++) acc[nt][e] = 0.f;

    issue(0, 0);
    for (int cc = 0; cc < 32; cc++) {
        const int cur = cc & 1;
        cp_wait0();
        __syncthreads();
        if (cc < 31) issue(cur ^ 1, 8 * (cc + 1));
        const float* Wc = Ws + cur * CV_WS;
        const float* Xc = Xs + cur * CV_XS;
#pragma unroll
        for (int ky = 0; ky < 3; ky++) {
#pragma unroll
            for (int kx = 0; kx < 3; kx++) {
                const int tap = ky * 3 + kx;
                uint32_t a0 = __float_as_uint(Wc[(16 * mo + g) * CV_SO + qb * 9 + tap]);
                uint32_t a1 = __float_as_uint(Wc[(16 * mo + g + 8) * CV_SO + qb * 9 + tap]);
                uint32_t a2 = __float_as_uint(Wc[(16 * mo + g) * CV_SO + (qb + 4) * 9 + tap]);
                uint32_t a3 = __float_as_uint(Wc[(16 * mo + g + 8) * CV_SO + (qb + 4) * 9 + tap]);
#pragma unroll
                for (int nt = 0; nt < 16; nt++) {
                    int r = 2 * sh + (nt >> 3) + ky;
                    int col = (nt & 7) * 8 + g + kx;
                    uint32_t b0 = __float_as_uint(Xc[qb * CV_XC + r * CV_XR + col]);
                    uint32_t b1 = __float_as_uint(Xc[(qb + 4) * CV_XC + r * CV_XR + col]);
                    mma8(acc[nt], a0, a1, a2, a3, b0, b1);
                }
            }
        }
        __syncthreads();
    }

    const float blo = bias[o0 + 16 * mo + g], bhi = bias[o0 + 16 * mo + g + 8];
#pragma unroll
    for (int nt = 0; nt < 16; nt++) {
        int h = 4 * hg + 2 * sh + (nt >> 3);
        int wv = (nt & 7) * 8 + 2 * qb;
        size_t base = (size_t)(o0 + 16 * mo + g) * NN + h * WW + wv;
        float2 v0; v0.x = acc[nt][0] + blo; v0.y = acc[nt][1] + blo;
        *(float2*)(Y + base) = v0;
        float2 v1; v1.x = acc[nt][2] + bhi; v1.y = acc[nt][3] + bhi;
        *(float2*)(Y + base + (size_t)8 * NN) = v1;
    }
}

// ---------------- flash attention v8: v4 core + ldmatrix PV + merged launch ------
// grid (NN/64, BB, 2): z = attention index. 256 threads, 8 warps = 4m x 2c-halves.
// BM=64, BN=64, occ 1, S/P register-resident, cp.async double buffer.
#define FA4_SMQ 0
#define FA4_QSTRIDE 36
#define FA4_SMK 2304
#define FA4_KSTRIDE 72
#define FA4_KBUF 2304
#define FA4_SMV (FA4_SMK + 2 * FA4_KBUF)
#define FA4_VSTRIDE 68
#define FA4_VBUF 17408
#define FA4_SMEM_FLOATS (FA4_SMV + 2 * FA4_VBUF)
#define FA4_SMEM_BYTES (FA4_SMEM_FLOATS * 4)   // 166912

__global__ __launch_bounds__(256, 1)
void flashattn_mma(const float* __restrict__ pk0, const float* __restrict__ pk1,
                   float* __restrict__ o1, float* __restrict__ o2, size_t bstr)
{
    extern __shared__ float sm[];
    float* Qs = sm + FA4_SMQ;

    const int tid  = threadIdx.x;
    const int w    = tid >> 5;
    const int lane = tid & 31;
    const int g    = lane >> 2;
    const int qb   = lane & 3;
    const int wm   = w & 3;
    const int cw   = w >> 2;
    const int i0   = blockIdx.x * 64;
    const int b    = blockIdx.y;
    const bool odd = qb & 1;
    const int srcA = (lane & ~3) | (qb >> 1);
    const int srcB = srcA + 2;

    const float *Q, *K, *V;
    float* O;
    if (blockIdx.z == 0) { Q = pk0 + (size_t)512 * NN; K = pk1 + (size_t)544 * NN; V = pk1; O = o1; }
    else                 { Q = pk1 + (size_t)512 * NN; K = pk0 + (size_t)544 * NN; V = pk0; O = o2; }

    const float* Qb = Q + (size_t)b * bstr;
    const float* Kb = K + (size_t)b * bstr;
    const float* Vb = V + (size_t)b * bstr;

    const uint32_t smb = (uint32_t)__cvta_generic_to_shared(sm);

    // prologue: tile 0 into buffer 0
    {
#pragma unroll
        for (int it = 0; it < 2; it++) {
            int cid = tid + it * 256;
            int d = cid >> 4, jc = (cid & 15) * 4;
            cpa16(smb + (FA4_SMK + d * FA4_KSTRIDE + jc) * 4, Kb + (size_t)d * NN + jc);
        }
#pragma unroll
        for (int it = 0; it < 16; it++) {
            int cid = tid + it * 256;
            int c = cid >> 4, jc = (cid & 15) * 4;
            cpa16(smb + (FA4_SMV + c * FA4_VSTRIDE + jc) * 4, Vb + (size_t)c * NN + jc);
        }
        cp_commit();
    }

    for (int idx = tid; idx < 64 * CKD; idx += 256) {
        int i = idx & 63, d = idx >> 6;
        Qs[i * FA4_QSTRIDE + d] = Qb[(size_t)d * NN + i0 + i];
    }
    __syncthreads();

    uint32_t aq[4][4];
#pragma unroll
    for (int kk = 0; kk < 4; kk++) {
        const int d0 = 8 * kk;
        const int br = 16 * wm;
        aq[kk][0] = __float_as_uint(Qs[(br + g) * FA4_QSTRIDE + d0 + qb]);
        aq[kk][1] = __float_as_uint(Qs[(br + g + 8) * FA4_QSTRIDE + d0 + qb]);
        aq[kk][2] = __float_as_uint(Qs[(br + g) * FA4_QSTRIDE + d0 + qb + 4]);
        aq[kk][3] = __float_as_uint(Qs[(br + g + 8) * FA4_QSTRIDE + d0 + qb + 4]);
    }

    float acc[16][4];
#pragma unroll
    for (int ct = 0; ct < 16; ct++)
#pragma unroll
        for (int e = 0; e < 4; e++) acc[ct][e] = 0.f;

    float mlo = -1e30f, mhi = -1e30f, llo = 0.f, lhi = 0.f;

    // ldmatrix lane-address components (within V tile): row = c-local, col group
    const int lm_row = lane & 7;          // row within 8x8 matrix
    const int lm_m   = lane >> 3;         // which 16B matrix (0..3)

    for (int t = 0; t < NN / 64; t++) {
        const int cur = t & 1;
        cp_wait0();
        __syncthreads();

        if (t + 1 < NN / 64) {
            const int j0n = (t + 1) * 64;
            const int nb  = 1 - cur;
#pragma unroll
            for (int it = 0; it < 2; it++) {
                int cid = tid + it * 256;
                int d = cid >> 4, jc = (cid & 15) * 4;
                cpa16(smb + (FA4_SMK + nb * FA4_KBUF + d * FA4_KSTRIDE + jc) * 4,
                      Kb + (size_t)d * NN + j0n + jc);
            }
#pragma unroll
            for (int it = 0; it < 16; it++) {
                int cid = tid + it * 256;
                int c = cid >> 4, jc = (cid & 15) * 4;
                cpa16(smb + (FA4_SMV + nb * FA4_VBUF + c * FA4_VSTRIDE + jc) * 4,
                      Vb + (size_t)c * NN + j0n + jc);
            }
            cp_commit();
        }

        const float* Ks = sm + FA4_SMK + cur * FA4_KBUF;   // [d][72]

        // ---- S = Q K^T ----
        float s[8][4];
#pragma unroll
        for (int nt = 0; nt < 8; nt++)
#pragma unroll
            for (int e = 0; e < 4; e++) s[nt][e] = 0.f;

#pragma unroll
        for (int kk = 0; kk < 4; kk++) {
            const int d0 = 8 * kk;
#pragma unroll
            for (int nt = 0; nt < 8; nt++) {
                uint32_t b0 = __float_as_uint(Ks[(d0 + qb) * FA4_KSTRIDE + 8 * nt + g]);
                uint32_t b1 = __float_as_uint(Ks[(d0 + qb + 4) * FA4_KSTRIDE + 8 * nt + g]);
                mma8(s[nt], aq[kk][0], aq[kk][1], aq[kk][2], aq[kk][3], b0, b1);
            }
        }

        // ---- online softmax in registers ----
        {
            float pmlo = -1e30f, pmhi = -1e30f;
#pragma unroll
            for (int nt = 0; nt < 8; nt++) {
                pmlo = fmaxf(pmlo, fmaxf(s[nt][0], s[nt][1]));
                pmhi = fmaxf(pmhi, fmaxf(s[nt][2], s[nt][3]));
            }
            pmlo = fmaxf(pmlo, __shfl_xor_sync(0xffffffffu, pmlo, 1));
            pmlo = fmaxf(pmlo, __shfl_xor_sync(0xffffffffu, pmlo, 2));
            pmhi = fmaxf(pmhi, __shfl_xor_sync(0xffffffffu, pmhi, 1));
            pmhi = fmaxf(pmhi, __shfl_xor_sync(0xffffffffu, pmhi, 2));

            float mlo_n = fmaxf(mlo, pmlo);
            float mhi_n = fmaxf(mhi, pmhi);
            float alo = __expf(mlo - mlo_n);
            float ahi = __expf(mhi - mhi_n);

            float slo = 0.f, shi = 0.f;
#pragma unroll
            for (int nt = 0; nt < 8; nt++) {
                s[nt][0] = __expf(s[nt][0] - mlo_n);
                s[nt][1] = __expf(s[nt][1] - mlo_n);
                s[nt][2] = __expf(s[nt][2] - mhi_n);
                s[nt][3] = __expf(s[nt][3] - mhi_n);
                slo += s[nt][0] + s[nt][1];
                shi += s[nt][2] + s[nt][3];
            }
            slo += __shfl_xor_sync(0xffffffffu, slo, 1);
            slo += __shfl_xor_sync(0xffffffffu, slo, 2);
            shi += __shfl_xor_sync(0xffffffffu, shi, 1);
            shi += __shfl_xor_sync(0xffffffffu, shi, 2);

            llo = llo * alo + slo;
            lhi = lhi * ahi + shi;
            mlo = mlo_n; mhi = mhi_n;

#pragma unroll
            for (int ct = 0; ct < 16; ct++) {
                acc[ct][0] *= alo; acc[ct][1] *= alo;
                acc[ct][2] *= ahi; acc[ct][3] *= ahi;
            }
        }

        // ---- O += P V : k-step pairs, B-frags via ldmatrix.x4 ----
#pragma unroll
        for (int kp = 0; kp < 4; kp++) {
            uint32_t aA[4], aB[4];
#pragma unroll
            for (int h = 0; h < 2; h++) {
                const int kk = 2 * kp + h;
                float x0 = __shfl_sync(0xffffffffu, s[kk][0], srcA);
                float x1 = __shfl_sync(0xffffffffu, s[kk][1], srcA);
                float y0 = __shfl_sync(0xffffffffu, s[kk][0], srcB);
                float y1 = __shfl_sync(0xffffffffu, s[kk][1], srcB);
                float z0 = __shfl_sync(0xffffffffu, s[kk][2], srcA);
                float z1 = __shfl_sync(0xffffffffu, s[kk][3], srcA);
                float w0 = __shfl_sync(0xffffffffu, s[kk][2], srcB);
                float w1 = __shfl_sync(0xffffffffu, s[kk][3], srcB);
                uint32_t* a = h ? aB : aA;
                a[0] = __float_as_uint(odd ? x1 : x0);
                a[1] = __float_as_uint(odd ? z1 : z0);
                a[2] = __float_as_uint(odd ? y1 : y0);
                a[3] = __float_as_uint(odd ? w1 : w0);
            }

            // base address: V row (128*cw + lm_row), col 16*kp + 4*lm_m
            uint32_t rowb = smb + (uint32_t)(FA4_SMV + cur * FA4_VBUF
                          + (128 * cw + lm_row) * FA4_VSTRIDE + 16 * kp + 4 * lm_m) * 4;
#pragma unroll
            for (int ct = 0; ct < 16; ct++) {
                uint32_t r0, r1, r2, r3;
                ldsm4(r0, r1, r2, r3, rowb + (uint32_t)(ct * 8 * FA4_VSTRIDE * 4));
                mma8(acc[ct], aA[0], aA[1], aA[2], aA[3], r0, r1);
                mma8(acc[ct], aB[0], aB[1], aB[2], aB[3], r2, r3);
            }
        }
    }
    __syncthreads();

    // ---- epilogue: normalize, stage via smem (reuse V buffers), store ----
    const float lilo = 1.f / llo;
    const float lihi = 1.f / lhi;
    float* smO = sm + FA4_SMV;

    for (int p = 0; p < 2; p++) {
        __syncthreads();
        if (cw == p) {
#pragma unroll
            for (int ct = 0; ct < 16; ct++) {
                const int rr = 16 * wm + g;
                const int cl = 8 * ct + 2 * qb;
                smO[cl * FA4_VSTRIDE + rr]           = acc[ct][0] * lilo;
                smO[(cl + 1) * FA4_VSTRIDE + rr]     = acc[ct][1] * lilo;
                smO[cl * FA4_VSTRIDE + rr + 8]       = acc[ct][2] * lihi;
                smO[(cl + 1) * FA4_VSTRIDE + rr + 8] = acc[ct][3] * lihi;
            }
        }
        __syncthreads();
        for (int idx = tid; idx < 128 * 16; idx += 256) {
            int c = idx >> 4, i4 = idx & 15;
            float4 v = *reinterpret_cast<float4*>(smO + c * FA4_VSTRIDE + i4 * 4);
            *reinterpret_cast<float4*>(
                O + ((size_t)(b * CC + 128 * p + c)) * NN + i0 + i4 * 4) = v;
        }
    }
}

// ---------------- combine: out = x + gamma*(attn + d1 + d3) ----------------------
__global__ void combine_kernel(const float* __restrict__ x, const float* __restrict__ o,
                               const float* __restrict__ d1, const float* __restrict__ d3,
                               const float* __restrict__ gamma, float* __restrict__ out)
{
    const int b = blockIdx.z;
    const float4* xp = (const float4*)(x + (size_t)b * CC * NN);
    const float4* op = (const float4*)(o + (size_t)b * CC * NN);
    const float4* dp = (const float4*)(d1 + (size_t)b * OP * NN);
    const float4* ep = (const float4*)(d3 + (size_t)b * CC * NN);
    float4* outp = (float4*)(out + (size_t)b * CC * NN);
    const float g = gamma[0];
    int i = blockIdx.x * blockDim.x + threadIdx.x;
    if (i < CC * NN / 4) {
        float4 xv = xp[i], ov = op[i], dv = dp[i], ev = ep[i];
        float4 r;
        r.x = xv.x + g * (ov.x + dv.x + ev.x);
        r.y = xv.y + g * (ov.y + dv.y + ev.y);
        r.z = xv.z + g * (ov.z + dv.z + ev.z);
        r.w = xv.w + g * (ov.w + dv.w + ev.w);
        outp[i] = r;
    }
}

// ---------------- host launcher --------------------------------------------------
extern "C" void kernel_launch(void* const* d_in, const int* in_sizes, int n_in,
                              void* d_out, int out_size)
{
    (void)in_sizes; (void)n_in; (void)out_size;

    const float* x1  = (const float*)d_in[0];
    const float* x2  = (const float*)d_in[1];
    const float* wq1 = (const float*)d_in[2];
    const float* bq1 = (const float*)d_in[3];
    const float* wk1 = (const float*)d_in[4];
    const float* bk1 = (const float*)d_in[5];
    const float* wv1 = (const float*)d_in[6];
    const float* bv1 = (const float*)d_in[7];
    const float* wq2 = (const float*)d_in[8];
    const float* bq2 = (const float*)d_in[9];
    const float* wk2 = (const float*)d_in[10];
    const float* bk2 = (const float*)d_in[11];
    const float* wv2 = (const float*)d_in[12];
    const float* bv2 = (const float*)d_in[13];
    const float* wd1 = (const float*)d_in[14];
    const float* bd1 = (const float*)d_in[15];
    const float* wd3 = (const float*)d_in[16];
    const float* bd3 = (const float*)d_in[17];
    const float* gm1 = (const float*)d_in[18];
    const float* gm2 = (const float*)d_in[19];
    float* out = (float*)d_out;

    float *p_pk, *p_d3, *p_o1, *p_o2;
    cudaGetSymbolAddress((void**)&p_pk, g_pk);
    cudaGetSymbolAddress((void**)&p_d3, g_d3);
    cudaGetSymbolAddress((void**)&p_o1, g_o1);
    cudaGetSymbolAddress((void**)&p_o2, g_o2);

    const size_t side_str = (size_t)BB * OP * NN;
    float* pk0 = p_pk;
    float* pk1 = p_pk + side_str;
    float* d3a = p_d3;
    float* d3b = p_d3 + (size_t)BB * CC * NN;
    const size_t bstr = (size_t)OP * NN;

    cudaFuncSetAttribute(conv3x3_mma,
                         cudaFuncAttributeMaxDynamicSharedMemorySize, CV_SMEM_BYTES);
    cudaFuncSetAttribute(flashattn_mma,
                         cudaFuncAttributeMaxDynamicSharedMemorySize, FA4_SMEM_BYTES);

    // 0-1: pack weights (per side)
    pack_weights<<<OP, 256>>>(wv1, bv1, wd1, bd1, wq1, bq1, wk1, bk1, 0);
    pack_weights<<<OP, 256>>>(wv2, bv2, wd1, bd1, wq2, bq2, wk2, bk2, 1);
    // 2: fused projections (both sides)
    proj_mma<<<dim3(NN / 128, OP / 64, 8), 256>>>(x1, x2);
    // 3-4: conv3x3 (per side)
    conv3x3_mma<<<dim3(CC / 64, HH / 4, BB), 256, CV_SMEM_BYTES>>>(x1, d3a, wd3, bd3);
    conv3x3_mma<<<dim3(CC / 64, HH / 4, BB), 256, CV_SMEM_BYTES>>>(x2, d3b, wd3, bd3);
    // 5: merged flash attention (both directions)  <-- profiled launch
    flashattn_mma<<<dim3(NN / 64, BB, 2), 256, FA4_SMEM_BYTES>>>(pk0, pk1, p_o1, p_o2, bstr);
    // 6-7: combine
    combine_kernel<<<dim3(1024, 1, BB), 256>>>(x1, p_o1, pk0 + (size_t)256 * NN,
                                               d3a, gm1, out);
    combine_kernel<<<dim3(1024, 1, BB), 256>>>(x2, p_o2, pk1 + (size_t)256 * NN,
                                               d3b, gm2, out + (size_t)BB * CC * NN);
}